// round 4
// baseline (speedup 1.0000x reference)
#include <cuda_runtime.h>
#include <cuda_bf16.h>
#include <cstddef>

// Enframe: x (8,2,480000) f32 -> out (8,4096,934) f32
//   out[b, c*2048 + k, t] = x[b, c, t*512 + k]
// Decompose k = 512*q + r (q in [0,4), r in [0,512)), bc = b*2+c:
//   out[bc, q*512 + r, t] = x[bc, (t+q)*512 + r]
// Tile: 128 t x 32 r per block; smem columns XOR-swizzled by bit5 of the slot
// row so the store phase's stride-2 row access is bank-conflict-free.

#define S_LEN     480000
#define T_OUT     934          // (480000 - 2048)/512 + 1
#define SLOTS     937          // max slot = 933 + 3 = 936
#define ROWS      2048         // per-bc output rows
#define R_PAD     33
#define T_TILE    128
#define SLOT_NEED 131          // 128 t + q shift (3)

// column swizzle: XOR rl by 16 when bit5 of the local slot row is set
#define SW(row)   ((((row) >> 5) & 1) << 4)

__global__ __launch_bounds__(256) void enframe_kernel(const float4* __restrict__ x4,
                                                      float* __restrict__ out) {
    __shared__ float tile[SLOT_NEED * R_PAD];   // 131*33*4 = 17292 B

    const int rt = blockIdx.x;   // 0..15  r base = rt*32
    const int tt = blockIdx.y;   // 0..7   t base = tt*128
    const int bc = blockIdx.z;   // 0..15
    const int tx = threadIdx.x;  // 0..31
    const int ty = threadIdx.y;  // 0..7

    const int tb = tt * T_TILE;
    const float4* __restrict__ xin = x4 + (size_t)bc * (S_LEN / 4);

    // ---- Load phase: LDG.128, swizzled scalar STS (conflict-free) ----
    const int c      = tx & 7;          // float4 column: r = rt*32 + 4c + j
    const int rowoff = tx >> 3;         // 0..3
    const bool interior = (tt < 7);     // t-tiles 0..6: no guards anywhere

#pragma unroll
    for (int p = 0; p < 5; ++p) {
        const int row = p * 32 + ty * 4 + rowoff;
        if (row < SLOT_NEED) {
            const int s = tb + row;
            float4 v = make_float4(0.f, 0.f, 0.f, 0.f);
            if (interior || s < SLOTS) v = xin[(size_t)s * 128 + rt * 8 + c];
            const int col0 = (4 * c) ^ SW(row);        // 4c..4c+3 stay in same 16-group
            float* dst = &tile[row * R_PAD + col0];
            dst[0] = v.x; dst[1] = v.y; dst[2] = v.z; dst[3] = v.w;
        }
    }
    __syncthreads();

    // ---- Store phase: warp ty -> (q = ty>>1, half = ty&1); lane = t pair ----
    const int q    = ty >> 1;
    const int half = ty & 1;
    const int t    = tb + half * 64 + 2 * tx;      // even t; pair (t, t+1)
    const int row  = half * 64 + 2 * tx + q;       // slot row for t (row+1 for t+1)

    const float* __restrict__ src0 = &tile[row * R_PAD];
    const float* __restrict__ src1 = &tile[(row + 1) * R_PAD];
    const int sw0 = SW(row);
    const int sw1 = SW(row + 1);

    float* __restrict__ o = out + (size_t)bc * ROWS * T_OUT
                                + (size_t)(q * 512 + rt * 32) * T_OUT + t;

    if (interior || t < T_OUT) {     // t even, T_OUT even -> pair fully valid
#pragma unroll
        for (int rl = 0; rl < 32; ++rl) {
            float2 v;
            v.x = src0[rl ^ sw0];     // conflict-free: paired lanes differ by ^16
            v.y = src1[rl ^ sw1];
            *(float2*)o = v;          // STG.64, 8B-aligned (934*4 % 8 == 0)
            o += T_OUT;
        }
    }
}

extern "C" void kernel_launch(void* const* d_in, const int* in_sizes, int n_in,
                              void* d_out, int out_size) {
    const float4* x = (const float4*)d_in[0];
    float* out = (float*)d_out;

    dim3 block(32, 8, 1);
    dim3 grid(16, 8, 16);   // (r tiles of 32, t tiles of 128, bc)
    enframe_kernel<<<grid, block>>>(x, out);
}